// round 1
// baseline (speedup 1.0000x reference)
#include <cuda_runtime.h>

#define BATCH 8192
#define T 50
#define F 17
#define HID 64
#define GATES 256     // 4*HID
#define INPD 34       // 2*F
#define BT 64         // batch rows per block
#define NB (BATCH/BT) // 128 blocks
#define NTHREADS 256

// Deterministic per-(t, block) loss partials (no atomics).
__device__ float g_num[T * NB];
__device__ float g_den[T * NB];

struct Smem {
    // transposed weights: [k][out]
    float Wtd[F][HID];     // gamma:  out 64, in 17
    float Wreg[HID][F];    // x_h:    out 17, in 64
    float Wih[INPD][GATES];
    float Whh[HID][GATES];
    float H[BT][HID];
    float C[BT][HID];
    float Inp[BT][INPD];   // [x_c | m]
    float X[BT][F];
    float M[BT][F];
    float D[BT][F];
    float btd[HID];
    float bih[GATES];      // b_ih + b_hh combined
    float Wout[HID];
    float red[16];
    float breg[F];
    float bout;
};

__device__ __forceinline__ float sigm(float x) {
    return __fdividef(1.0f, 1.0f + __expf(-x));
}
__device__ __forceinline__ float tanh_acc(float x) {
    // accurate-enough tanh via exp: 2/(1+exp(-2x)) - 1
    return __fdividef(2.0f, 1.0f + __expf(-2.0f * x)) - 1.0f;
}

__global__ void __launch_bounds__(NTHREADS, 1)
grud_kernel(const float* __restrict__ values,
            const float* __restrict__ masks,
            const float* __restrict__ deltas,
            const float* __restrict__ Wtd, const float* __restrict__ btd,
            const float* __restrict__ Wreg, const float* __restrict__ breg,
            const float* __restrict__ Wih, const float* __restrict__ Whh,
            const float* __restrict__ bih, const float* __restrict__ bhh,
            const float* __restrict__ Wout, const float* __restrict__ bout,
            float* __restrict__ out_imp,   // [B, T, F]
            float* __restrict__ out_yh)    // [B]
{
    extern __shared__ float smem_raw[];
    Smem& s = *reinterpret_cast<Smem*>(smem_raw);
    const int tid = threadIdx.x;
    const int bb = blockIdx.x * BT;

    // ---- load + transpose weights into shared ----
    for (int i = tid; i < F * HID; i += NTHREADS) {
        int k = i / HID, j = i % HID;
        s.Wtd[k][j] = Wtd[j * F + k];
    }
    for (int i = tid; i < HID * F; i += NTHREADS) {
        int k = i / F, f = i % F;
        s.Wreg[k][f] = Wreg[f * HID + k];
    }
    for (int i = tid; i < INPD * GATES; i += NTHREADS) {
        int k = i / GATES, j = i % GATES;
        s.Wih[k][j] = Wih[j * INPD + k];
    }
    for (int i = tid; i < HID * GATES; i += NTHREADS) {
        int k = i / GATES, j = i % GATES;
        s.Whh[k][j] = Whh[j * HID + k];
    }
    if (tid < HID) s.btd[tid] = btd[tid];
    if (tid < F)   s.breg[tid] = breg[tid];
    if (tid < GATES) s.bih[tid] = bih[tid] + bhh[tid];
    if (tid < HID) s.Wout[tid] = Wout[tid];
    if (tid == 0)  s.bout = bout[0];
    for (int i = tid; i < BT * HID; i += NTHREADS) {
        s.H[i / HID][i % HID] = 0.0f;
        s.C[i / HID][i % HID] = 0.0f;
    }
    __syncthreads();

    const int w = tid >> 5;        // warp id 0..7 -> owns rows r0..r0+7
    const int l = tid & 31;        // lane -> owns hidden units h0, h0+1
    const int r0 = w * 8;
    const int h0 = l * 2;

    for (int t = 0; t < T; t++) {
        // ---- phase 1: load x, m, d for this timestep ----
        for (int o = tid; o < BT * F; o += NTHREADS) {
            int r = o / F, f = o % F;
            int base = (bb + r) * (T * F) + t * F + f;
            float xv = values[base];
            xv = (xv != xv) ? 0.0f : xv;   // nan -> 0
            float mv = masks[base];
            s.X[r][f] = xv;
            s.M[r][f] = mv;
            s.D[r][f] = deltas[base];
            s.Inp[r][F + f] = mv;
        }
        __syncthreads();

        // ---- phase 2: gamma = exp(-relu(d@Wtd^T + btd)); h *= gamma ----
        {
            float a0[8], a1[8];
            #pragma unroll
            for (int i = 0; i < 8; i++) { a0[i] = s.btd[h0]; a1[i] = s.btd[h0 + 1]; }
            #pragma unroll
            for (int k = 0; k < F; k++) {
                float2 wv = *(const float2*)&s.Wtd[k][h0];
                #pragma unroll
                for (int i = 0; i < 8; i++) {
                    float dv = s.D[r0 + i][k];
                    a0[i] += dv * wv.x;
                    a1[i] += dv * wv.y;
                }
            }
            #pragma unroll
            for (int i = 0; i < 8; i++) {
                float g0 = __expf(-fmaxf(a0[i], 0.0f));
                float g1 = __expf(-fmaxf(a1[i], 0.0f));
                float2* hp = (float2*)&s.H[r0 + i][h0];
                float2 hv = *hp;
                hv.x *= g0; hv.y *= g1;
                *hp = hv;
            }
        }
        __syncthreads();

        // ---- phase 3: x_h = h@Wreg^T + breg; x_c; loss partials; imputation ----
        float lnum = 0.0f, lden = 0.0f;
        for (int o = tid; o < BT * F; o += NTHREADS) {
            int r = o / F, f = o % F;
            float acc = s.breg[f];
            #pragma unroll 8
            for (int k = 0; k < HID; k++) acc += s.H[r][k] * s.Wreg[k][f];
            float xv = s.X[r][f];
            float mv = s.M[r][f];
            float xc = mv * xv + (1.0f - mv) * acc;
            s.Inp[r][f] = xc;
            lnum += fabsf(xv - acc) * mv;
            lden += mv;
            out_imp[(bb + r) * (T * F) + t * F + f] = xc;
        }
        // warp reduce then stage per-warp partials
        #pragma unroll
        for (int ofs = 16; ofs > 0; ofs >>= 1) {
            lnum += __shfl_down_sync(0xFFFFFFFFu, lnum, ofs);
            lden += __shfl_down_sync(0xFFFFFFFFu, lden, ofs);
        }
        if (l == 0) { s.red[w] = lnum; s.red[8 + w] = lden; }
        __syncthreads();
        if (tid == 0) {
            float n = 0.0f, d = 0.0f;
            #pragma unroll
            for (int i = 0; i < 8; i++) { n += s.red[i]; d += s.red[8 + i]; }
            g_num[t * NB + blockIdx.x] = n;
            g_den[t * NB + blockIdx.x] = d;
        }

        // ---- phase 4: gates GEMM + LSTM update ----
        {
            float ai0[8], ai1[8], af0[8], af1[8], ag0[8], ag1[8], ao0[8], ao1[8];
            #pragma unroll
            for (int i = 0; i < 8; i++) {
                ai0[i] = s.bih[h0];           ai1[i] = s.bih[h0 + 1];
                af0[i] = s.bih[64 + h0];      af1[i] = s.bih[64 + h0 + 1];
                ag0[i] = s.bih[128 + h0];     ag1[i] = s.bih[128 + h0 + 1];
                ao0[i] = s.bih[192 + h0];     ao1[i] = s.bih[192 + h0 + 1];
            }
            #pragma unroll 2
            for (int k = 0; k < INPD; k++) {
                float2 wi = *(const float2*)&s.Wih[k][h0];
                float2 wf = *(const float2*)&s.Wih[k][64 + h0];
                float2 wg = *(const float2*)&s.Wih[k][128 + h0];
                float2 wo = *(const float2*)&s.Wih[k][192 + h0];
                #pragma unroll
                for (int i = 0; i < 8; i++) {
                    float v = s.Inp[r0 + i][k];
                    ai0[i] += v * wi.x; ai1[i] += v * wi.y;
                    af0[i] += v * wf.x; af1[i] += v * wf.y;
                    ag0[i] += v * wg.x; ag1[i] += v * wg.y;
                    ao0[i] += v * wo.x; ao1[i] += v * wo.y;
                }
            }
            #pragma unroll 2
            for (int k = 0; k < HID; k++) {
                float2 wi = *(const float2*)&s.Whh[k][h0];
                float2 wf = *(const float2*)&s.Whh[k][64 + h0];
                float2 wg = *(const float2*)&s.Whh[k][128 + h0];
                float2 wo = *(const float2*)&s.Whh[k][192 + h0];
                #pragma unroll
                for (int i = 0; i < 8; i++) {
                    float v = s.H[r0 + i][k];
                    ai0[i] += v * wi.x; ai1[i] += v * wi.y;
                    af0[i] += v * wf.x; af1[i] += v * wf.y;
                    ag0[i] += v * wg.x; ag1[i] += v * wg.y;
                    ao0[i] += v * wo.x; ao1[i] += v * wo.y;
                }
            }
            #pragma unroll
            for (int i = 0; i < 8; i++) {
                float2* cp = (float2*)&s.C[r0 + i][h0];
                float2 cv = *cp;
                float iv0 = sigm(ai0[i]), iv1 = sigm(ai1[i]);
                float fv0 = sigm(af0[i]), fv1 = sigm(af1[i]);
                float gv0 = tanh_acc(ag0[i]), gv1 = tanh_acc(ag1[i]);
                float ov0 = sigm(ao0[i]), ov1 = sigm(ao1[i]);
                float c0 = fv0 * cv.x + iv0 * gv0;
                float c1 = fv1 * cv.y + iv1 * gv1;
                cv.x = c0; cv.y = c1;
                *cp = cv;
                float2* hp = (float2*)&s.H[r0 + i][h0];
                float2 hv;
                hv.x = ov0 * tanh_acc(c0);
                hv.y = ov1 * tanh_acc(c1);
                *hp = hv;
            }
        }
        __syncthreads();
    }

    // ---- y_h = h_final @ Wout^T + bout ----
    if (tid < BT) {
        float acc = s.bout;
        #pragma unroll 8
        for (int k = 0; k < HID; k++) acc += s.H[tid][k] * s.Wout[k];
        out_yh[bb + tid] = acc;
    }
}

__global__ void grud_finalize(float* __restrict__ out_loss) {
    __shared__ float sv[64];
    int t = threadIdx.x;
    float v = 0.0f;
    if (t < T) {
        float n = 0.0f, d = 0.0f;
        for (int b = 0; b < NB; b++) {
            n += g_num[t * NB + b];
            d += g_den[t * NB + b];
        }
        v = n / (d + 1e-5f);
    }
    sv[t] = v;
    __syncthreads();
    for (int sft = 32; sft > 0; sft >>= 1) {
        if (t < sft) sv[t] += sv[t + sft];
        __syncthreads();
    }
    if (t == 0) out_loss[0] = sv[0];
}

extern "C" void kernel_launch(void* const* d_in, const int* in_sizes, int n_in,
                              void* d_out, int out_size) {
    const float* values = (const float*)d_in[0];
    const float* masks  = (const float*)d_in[1];
    const float* deltas = (const float*)d_in[2];
    const float* Wtd    = (const float*)d_in[3];
    const float* btd    = (const float*)d_in[4];
    const float* Wreg   = (const float*)d_in[5];
    const float* breg   = (const float*)d_in[6];
    const float* Wih    = (const float*)d_in[7];
    const float* Whh    = (const float*)d_in[8];
    const float* bih    = (const float*)d_in[9];
    const float* bhh    = (const float*)d_in[10];
    const float* Wout   = (const float*)d_in[11];
    const float* bout   = (const float*)d_in[12];

    float* out = (float*)d_out;
    float* out_loss = out;                       // [1]
    float* out_imp  = out + 1;                   // [B, T, F]
    float* out_yh   = out + 1 + BATCH * T * F;   // [B, 1]

    cudaFuncSetAttribute(grud_kernel,
                         cudaFuncAttributeMaxDynamicSharedMemorySize,
                         (int)sizeof(Smem));
    grud_kernel<<<NB, NTHREADS, sizeof(Smem)>>>(
        values, masks, deltas, Wtd, btd, Wreg, breg,
        Wih, Whh, bih, bhh, Wout, bout, out_imp, out_yh);
    grud_finalize<<<1, 64>>>(out_loss);
}